// round 2
// baseline (speedup 1.0000x reference)
#include <cuda_runtime.h>
#include <cuda_bf16.h>

#define TT    2048
#define BB    32
#define DD    512
#define HH    512
#define BTR   (BB * TT)          // 65536
#define NCTA  128

// ---------------- device scratch ----------------
__device__ float g_proj[(size_t)BTR * DD];               // 128 MB
__device__ float g_pre[(size_t)TT * HH * BB * 4];        // 512 MB  [t][j][b][gate]
__device__ float g_wcat[DD * 4 * HH];                    // 4 MB    [k][c], c = j*4+g
__device__ float g_bcat[4 * HH];
__device__ float g_hbuf[2][BB * HH];
__device__ unsigned int g_bar;

// ---------------- packed f32x2 helpers ----------------
__device__ __forceinline__ unsigned long long ffma2(unsigned long long a,
                                                    unsigned long long b,
                                                    unsigned long long c) {
    unsigned long long d;
    asm("fma.rn.f32x2 %0, %1, %2, %3;" : "=l"(d) : "l"(a), "l"(b), "l"(c));
    return d;
}
__device__ __forceinline__ unsigned long long pack2(float x) {
    unsigned long long d;
    asm("mov.b64 %0, {%1, %1};" : "=l"(d) : "f"(x));
    return d;
}
__device__ __forceinline__ float2 unpack2(unsigned long long v) {
    float2 r;
    asm("mov.b64 {%0, %1}, %2;" : "=f"(r.x), "=f"(r.y) : "l"(v));
    return r;
}

__device__ __forceinline__ float sig_(float x) {
    return __fdividef(1.f, 1.f + __expf(-x));
}
__device__ __forceinline__ float tanh_(float x) {
    return 1.f - __fdividef(2.f, __expf(2.f * x) + 1.f);
}

// ---------------- pack weights + init state ----------------
__global__ void pack_kernel(const float* __restrict__ Wf, const float* __restrict__ Wi,
                            const float* __restrict__ Wc, const float* __restrict__ Wo,
                            const float* __restrict__ bf, const float* __restrict__ bi,
                            const float* __restrict__ bc, const float* __restrict__ bo) {
    int idx = blockIdx.x * 256 + threadIdx.x;
    if (idx < DD * 4 * HH) {
        int k = idx >> 11;         // input-half row of W_*
        int c = idx & 2047;        // c = j*4+g
        int j = c >> 2, g = c & 3;
        const float* W = (g == 0) ? Wf : (g == 1) ? Wi : (g == 2) ? Wc : Wo;
        g_wcat[idx] = W[(size_t)k * HH + j];
    }
    if (idx < 4 * HH) {
        int j = idx >> 2, g = idx & 3;
        const float* bv = (g == 0) ? bf : (g == 1) ? bi : (g == 2) ? bc : bo;
        g_bcat[idx] = bv[j];
    }
    if (idx < BB * HH) g_hbuf[0][idx] = 0.f;
    if (idx == 0) g_bar = 0u;
}

// ---------------- fp32 SIMT GEMM, f32x2 accumulation ----------------
// C[M x N] = A[M x 512] * B[512 x N] (+bias). BM=BN=128, BK=16, 256 thr, 8x8 tiles.
// stage 0: A=X, B=W_p, ldb=512, out = g_proj[r*512+c] = tanh(.)
// stage 1: A=g_proj, B=g_wcat, ldb=2048, out = g_pre [t][j][b][g]
__global__ __launch_bounds__(256, 2) void gemm_kernel(
    int stage, const float* __restrict__ Aext, const float* __restrict__ Bext,
    const float* __restrict__ biasext) {
    __shared__ __align__(16) float As[16][132];
    __shared__ __align__(16) float Bs[16][128];

    const float* A    = (stage == 0) ? Aext    : g_proj;
    const float* B    = (stage == 0) ? Bext    : g_wcat;
    const float* bias = (stage == 0) ? biasext : g_bcat;
    float* out = (stage == 0) ? g_proj : g_pre;
    const int ldb = (stage == 0) ? 512 : 2048;

    const int tid = threadIdx.x;
    const int m0 = blockIdx.y * 128;
    const int n0 = blockIdx.x * 128;
    const int tm = tid >> 4, tn = tid & 15;

    unsigned long long acc[4][8];
    #pragma unroll
    for (int p = 0; p < 4; p++)
        #pragma unroll
        for (int n = 0; n < 8; n++) acc[p][n] = 0ull;

    for (int k0 = 0; k0 < 512; k0 += 16) {
        #pragma unroll
        for (int i = 0; i < 2; i++) {
            int idx = tid + i * 256;
            int row = idx >> 2, c4 = idx & 3;
            float4 v = *(const float4*)(A + (size_t)(m0 + row) * 512 + k0 + c4 * 4);
            As[c4 * 4 + 0][row] = v.x;
            As[c4 * 4 + 1][row] = v.y;
            As[c4 * 4 + 2][row] = v.z;
            As[c4 * 4 + 3][row] = v.w;
        }
        #pragma unroll
        for (int i = 0; i < 2; i++) {
            int idx = tid + i * 256;
            int row = idx >> 5, c4 = idx & 31;
            *(float4*)&Bs[row][c4 * 4] =
                *(const float4*)(B + (size_t)(k0 + row) * ldb + n0 + c4 * 4);
        }
        __syncthreads();
        #pragma unroll
        for (int kk = 0; kk < 16; kk++) {
            ulonglong2 aA = *(const ulonglong2*)&As[kk][tm * 8];
            ulonglong2 aB = *(const ulonglong2*)&As[kk][tm * 8 + 4];
            float4 b0 = *(const float4*)&Bs[kk][tn * 8];
            float4 b1 = *(const float4*)&Bs[kk][tn * 8 + 4];
            unsigned long long bd[8];
            bd[0] = pack2(b0.x); bd[1] = pack2(b0.y); bd[2] = pack2(b0.z); bd[3] = pack2(b0.w);
            bd[4] = pack2(b1.x); bd[5] = pack2(b1.y); bd[6] = pack2(b1.z); bd[7] = pack2(b1.w);
            #pragma unroll
            for (int n = 0; n < 8; n++) {
                acc[0][n] = ffma2(aA.x, bd[n], acc[0][n]);
                acc[1][n] = ffma2(aA.y, bd[n], acc[1][n]);
                acc[2][n] = ffma2(aB.x, bd[n], acc[2][n]);
                acc[3][n] = ffma2(aB.y, bd[n], acc[3][n]);
            }
        }
        __syncthreads();
    }

    float4 bs0 = *(const float4*)&bias[n0 + tn * 8];
    float4 bs1 = *(const float4*)&bias[n0 + tn * 8 + 4];
    float bv[8] = {bs0.x, bs0.y, bs0.z, bs0.w, bs1.x, bs1.y, bs1.z, bs1.w};

    #pragma unroll
    for (int p = 0; p < 4; p++) {
        int r0 = m0 + tm * 8 + 2 * p;   // row pair (r0, r0+1)
        #pragma unroll
        for (int jj = 0; jj < 2; jj++) {
            float2 u0 = unpack2(acc[p][jj * 4 + 0]);
            float2 u1 = unpack2(acc[p][jj * 4 + 1]);
            float2 u2 = unpack2(acc[p][jj * 4 + 2]);
            float2 u3 = unpack2(acc[p][jj * 4 + 3]);
            float4 lo4, hi4;
            lo4.x = u0.x + bv[jj * 4 + 0]; hi4.x = u0.y + bv[jj * 4 + 0];
            lo4.y = u1.x + bv[jj * 4 + 1]; hi4.y = u1.y + bv[jj * 4 + 1];
            lo4.z = u2.x + bv[jj * 4 + 2]; hi4.z = u2.y + bv[jj * 4 + 2];
            lo4.w = u3.x + bv[jj * 4 + 3]; hi4.w = u3.y + bv[jj * 4 + 3];
            if (stage == 0) {
                lo4.x = tanh_(lo4.x); lo4.y = tanh_(lo4.y);
                lo4.z = tanh_(lo4.z); lo4.w = tanh_(lo4.w);
                hi4.x = tanh_(hi4.x); hi4.y = tanh_(hi4.y);
                hi4.z = tanh_(hi4.z); hi4.w = tanh_(hi4.w);
                int c0 = n0 + tn * 8 + jj * 4;
                *(float4*)(out + (size_t)r0 * 512 + c0)       = lo4;
                *(float4*)(out + (size_t)(r0 + 1) * 512 + c0) = hi4;
            } else {
                int b  = r0 >> 11;
                int t0 = r0 & 2047;
                int jglob = ((n0 + tn * 8) >> 2) + jj;
                *(float4*)(out + (((size_t)t0 * 512 + jglob) * 32 + b) * 4)       = lo4;
                *(float4*)(out + (((size_t)(t0 + 1) * 512 + jglob) * 32 + b) * 4) = hi4;
            }
        }
    }
}

// ---------------- persistent recurrent scan ----------------
// 128 CTAs x 256 threads; CTA owns 4 hidden columns j0..j0+3 (all 4 gates, all 32 b).
// SMEM: h_s[32][513] (65664 B) | w_s 4j*512k ulonglong2 (32768 B)
//       | part 8w*32b*4j uint4 (16384 B) | c_s 32b*4j (512 B)  = 115328 B
#define SCAN_SMEM 115328

__global__ __launch_bounds__(256, 1) void lstm_scan_kernel(
    const float* __restrict__ Wf, const float* __restrict__ Wi,
    const float* __restrict__ Wc, const float* __restrict__ Wo,
    float* __restrict__ out) {
    extern __shared__ __align__(16) char smraw[];
    float*      h_s  = (float*)smraw;                               // [32][513]
    ulonglong2* w_s  = (ulonglong2*)(smraw + 65664);                // [j][k]
    uint4*      part = (uint4*)(smraw + 65664 + 32768);             // [w][b][j]
    float*      c_s  = (float*)(smraw + 65664 + 32768 + 16384);     // [b*4+j]

    const int tid  = threadIdx.x;
    const int lane = tid & 31;
    const int wrp  = tid >> 5;
    const int j0   = blockIdx.x * 4;

    // cache recurrent weights (rows 512..1023), packed (f,i)(c,o) per (j,k)
    for (int idx = tid; idx < 4 * 512; idx += 256) {
        int j = idx >> 9, k = idx & 511;
        size_t off = (size_t)(512 + k) * HH + (j0 + j);
        uint4 w;
        w.x = __float_as_uint(Wf[off]); w.y = __float_as_uint(Wi[off]);
        w.z = __float_as_uint(Wc[off]); w.w = __float_as_uint(Wo[off]);
        ((uint4*)w_s)[j * 512 + k] = w;
    }
    if (tid < 128) c_s[tid] = 0.f;

    int cur = 0;
    for (int t = 0; t < TT; t++) {
        // broadcast h into smem (row stride 513 -> conflict-free lane=b reads)
        const float4* hg = (const float4*)g_hbuf[cur];
        #pragma unroll
        for (int i = 0; i < 16; i++) {
            int lin = tid + i * 256;            // 0..4095 float4 ids
            float4 v = hg[lin];
            int b = lin >> 7;
            int k = (lin & 127) * 4;
            float* dst = h_s + b * 513 + k;
            dst[0] = v.x; dst[1] = v.y; dst[2] = v.z; dst[3] = v.w;
        }
        // prefetch this step's precomputed input-half pre-activations
        float4 pre4 = make_float4(0.f, 0.f, 0.f, 0.f);
        if (tid < 128) {
            int rj = tid & 3, rb = tid >> 2;
            pre4 = *(const float4*)(g_pre + (((size_t)t * 512 + j0 + rj) * 32 + rb) * 4);
        }
        __syncthreads();

        // warp wrp: k in [wrp*64, wrp*64+64); lane = batch b
        unsigned long long s00 = 0, s01 = 0, s10 = 0, s11 = 0;
        unsigned long long s20 = 0, s21 = 0, s30 = 0, s31 = 0;
        const float* hrow = h_s + lane * 513 + wrp * 64;
        const ulonglong2* wp = w_s + wrp * 64;
        #pragma unroll 8
        for (int kk = 0; kk < 64; kk++) {
            unsigned long long hv = pack2(hrow[kk]);
            ulonglong2 w0 = wp[kk];
            ulonglong2 w1 = wp[512 + kk];
            ulonglong2 w2 = wp[1024 + kk];
            ulonglong2 w3 = wp[1536 + kk];
            s00 = ffma2(hv, w0.x, s00); s01 = ffma2(hv, w0.y, s01);
            s10 = ffma2(hv, w1.x, s10); s11 = ffma2(hv, w1.y, s11);
            s20 = ffma2(hv, w2.x, s20); s21 = ffma2(hv, w2.y, s31 * 0 + s21);
            s30 = ffma2(hv, w3.x, s30); s31 = ffma2(hv, w3.y, s31);
        }
        {
            uint4* pp = part + (wrp * 32 + lane) * 4;
            float2 a, b2;
            a = unpack2(s00); b2 = unpack2(s01);
            pp[0] = make_uint4(__float_as_uint(a.x), __float_as_uint(a.y),
                               __float_as_uint(b2.x), __float_as_uint(b2.y));
            a = unpack2(s10); b2 = unpack2(s11);
            pp[1] = make_uint4(__float_as_uint(a.x), __float_as_uint(a.y),
                               __float_as_uint(b2.x), __float_as_uint(b2.y));
            a = unpack2(s20); b2 = unpack2(s21);
            pp[2] = make_uint4(__float_as_uint(a.x), __float_as_uint(a.y),
                               __float_as_uint(b2.x), __float_as_uint(b2.y));
            a = unpack2(s30); b2 = unpack2(s31);
            pp[3] = make_uint4(__float_as_uint(a.x), __float_as_uint(a.y),
                               __float_as_uint(b2.x), __float_as_uint(b2.y));
        }
        __syncthreads();

        int nxt = cur ^ 1;
        if (tid < 128) {
            int rj = tid & 3, rb = tid >> 2;
            float rf = 0.f, ri = 0.f, rc = 0.f, ro = 0.f;
            #pragma unroll
            for (int w = 0; w < 8; w++) {
                uint4 v = part[(w * 32 + rb) * 4 + rj];
                rf += __uint_as_float(v.x);
                ri += __uint_as_float(v.y);
                rc += __uint_as_float(v.z);
                ro += __uint_as_float(v.w);
            }
            float f  = sig_(pre4.x + rf);
            float ii = sig_(pre4.y + ri);
            float cg = tanh_(pre4.z + rc);
            float o  = sig_(pre4.w + ro);
            float cn = f * c_s[tid] + ii * cg;
            c_s[tid] = cn;
            float h = o * tanh_(cn);
            g_hbuf[nxt][rb * HH + j0 + rj] = h;
            out[((size_t)rb * TT + t) * HH + j0 + rj] = h;
        }
        // grid barrier (release h writes, wait for all CTAs)
        __threadfence();
        __syncthreads();
        if (tid == 0) {
            atomicAdd(&g_bar, 1u);
            unsigned tgt = (unsigned)NCTA * (unsigned)(t + 1), v;
            do {
                asm volatile("ld.acquire.gpu.u32 %0, [%1];" : "=r"(v) : "l"(&g_bar) : "memory");
            } while (v < tgt);
        }
        __syncthreads();
        __threadfence();
        cur = nxt;
    }
}

extern "C" void kernel_launch(void* const* d_in, const int* in_sizes, int n_in,
                              void* d_out, int out_size) {
    const float* X   = (const float*)d_in[0];
    const float* W_p = (const float*)d_in[1];
    const float* b_p = (const float*)d_in[2];
    const float* W_f = (const float*)d_in[3];
    const float* b_f = (const float*)d_in[4];
    const float* W_i = (const float*)d_in[5];
    const float* b_i = (const float*)d_in[6];
    const float* W_c = (const float*)d_in[7];
    const float* b_c = (const float*)d_in[8];
    const float* W_o = (const float*)d_in[9];
    const float* b_o = (const float*)d_in[10];
    float* out = (float*)d_out;

    static bool attr_done = false;
    cudaFuncSetAttribute(lstm_scan_kernel,
                         cudaFuncAttributeMaxDynamicSharedMemorySize, SCAN_SMEM);
    (void)attr_done;

    pack_kernel<<<4096, 256>>>(W_f, W_i, W_c, W_o, b_f, b_i, b_c, b_o);
    gemm_kernel<<<dim3(4, 512), 256>>>(0, X, W_p, b_p);
    gemm_kernel<<<dim3(16, 512), 256>>>(1, nullptr, nullptr, nullptr);
    lstm_scan_kernel<<<NCTA, 256, SCAN_SMEM>>>(W_f, W_i, W_c, W_o, out);
}

// round 4
// speedup vs baseline: 1.1576x; 1.1576x over previous
#include <cuda_runtime.h>
#include <cuda_bf16.h>

#define TT    2048
#define BB    32
#define DD    512
#define HH    512
#define BTR   (BB * TT)          // 65536
#define NCTA  128

// ---------------- device scratch ----------------
__device__ float g_proj[(size_t)BTR * DD];               // 128 MB
__device__ float g_pre[(size_t)TT * HH * BB * 4];        // 512 MB  [t][j][b][gate]
__device__ float g_wcat[DD * 4 * HH];                    // 4 MB    [k][c], c = j*4+g
__device__ float g_bcat[4 * HH];
__device__ __align__(16) float g_hbuf[2][HH * BB];       // [k][b] layout
__device__ unsigned int g_bar;

// ---------------- packed f32x2 helpers ----------------
__device__ __forceinline__ unsigned long long ffma2(unsigned long long a,
                                                    unsigned long long b,
                                                    unsigned long long c) {
    unsigned long long d;
    asm("fma.rn.f32x2 %0, %1, %2, %3;" : "=l"(d) : "l"(a), "l"(b), "l"(c));
    return d;
}
__device__ __forceinline__ unsigned long long pack2(float x) {
    unsigned long long d;
    asm("mov.b64 %0, {%1, %1};" : "=l"(d) : "f"(x));
    return d;
}
__device__ __forceinline__ float2 unpack2(unsigned long long v) {
    float2 r;
    asm("mov.b64 {%0, %1}, %2;" : "=f"(r.x), "=f"(r.y) : "l"(v));
    return r;
}
__device__ __forceinline__ float4 ldcv4(const float* p) {
    float4 v;
    asm volatile("ld.global.cv.v4.f32 {%0,%1,%2,%3}, [%4];"
                 : "=f"(v.x), "=f"(v.y), "=f"(v.z), "=f"(v.w) : "l"(p));
    return v;
}

__device__ __forceinline__ float sig_(float x) {
    return __fdividef(1.f, 1.f + __expf(-x));
}
__device__ __forceinline__ float tanh_(float x) {
    return 1.f - __fdividef(2.f, __expf(2.f * x) + 1.f);
}

// ---------------- pack weights + init state ----------------
__global__ void pack_kernel(const float* __restrict__ Wf, const float* __restrict__ Wi,
                            const float* __restrict__ Wc, const float* __restrict__ Wo,
                            const float* __restrict__ bf, const float* __restrict__ bi,
                            const float* __restrict__ bc, const float* __restrict__ bo) {
    int idx = blockIdx.x * 256 + threadIdx.x;
    if (idx < DD * 4 * HH) {
        int k = idx >> 11;         // input-half row of W_*
        int c = idx & 2047;        // c = j*4+g
        int j = c >> 2, g = c & 3;
        const float* W = (g == 0) ? Wf : (g == 1) ? Wi : (g == 2) ? Wc : Wo;
        g_wcat[idx] = W[(size_t)k * HH + j];
    }
    if (idx < 4 * HH) {
        int j = idx >> 2, g = idx & 3;
        const float* bv = (g == 0) ? bf : (g == 1) ? bi : (g == 2) ? bc : bo;
        g_bcat[idx] = bv[j];
    }
    if (idx < HH * BB) g_hbuf[0][idx] = 0.f;
    if (idx == 0) g_bar = 0u;
}

// ---------------- fp32 SIMT GEMM, f32x2 accumulation ----------------
// C[M x N] = A[M x 512] * B[512 x N] (+bias). BM=BN=128, BK=16, 256 thr, 8x8 tiles.
// stage 0: A=X, B=W_p, ldb=512, out = g_proj[r*512+c] = tanh(.)
// stage 1: A=g_proj, B=g_wcat, ldb=2048, out = g_pre [t][j][b][g]
__global__ __launch_bounds__(256, 2) void gemm_kernel(
    int stage, const float* __restrict__ Aext, const float* __restrict__ Bext,
    const float* __restrict__ biasext) {
    __shared__ __align__(16) float As[16][132];
    __shared__ __align__(16) float Bs[16][128];

    const float* A    = (stage == 0) ? Aext    : g_proj;
    const float* B    = (stage == 0) ? Bext    : g_wcat;
    const float* bias = (stage == 0) ? biasext : g_bcat;
    float* out = (stage == 0) ? g_proj : g_pre;
    const int ldb = (stage == 0) ? 512 : 2048;

    const int tid = threadIdx.x;
    const int m0 = blockIdx.y * 128;
    const int n0 = blockIdx.x * 128;
    const int tm = tid >> 4, tn = tid & 15;

    unsigned long long acc[4][8];
    #pragma unroll
    for (int p = 0; p < 4; p++)
        #pragma unroll
        for (int n = 0; n < 8; n++) acc[p][n] = 0ull;

    for (int k0 = 0; k0 < 512; k0 += 16) {
        #pragma unroll
        for (int i = 0; i < 2; i++) {
            int idx = tid + i * 256;
            int row = idx >> 2, c4 = idx & 3;
            float4 v = *(const float4*)(A + (size_t)(m0 + row) * 512 + k0 + c4 * 4);
            As[c4 * 4 + 0][row] = v.x;
            As[c4 * 4 + 1][row] = v.y;
            As[c4 * 4 + 2][row] = v.z;
            As[c4 * 4 + 3][row] = v.w;
        }
        #pragma unroll
        for (int i = 0; i < 2; i++) {
            int idx = tid + i * 256;
            int row = idx >> 5, c4 = idx & 31;
            *(float4*)&Bs[row][c4 * 4] =
                *(const float4*)(B + (size_t)(k0 + row) * ldb + n0 + c4 * 4);
        }
        __syncthreads();
        #pragma unroll
        for (int kk = 0; kk < 16; kk++) {
            ulonglong2 aA = *(const ulonglong2*)&As[kk][tm * 8];
            ulonglong2 aB = *(const ulonglong2*)&As[kk][tm * 8 + 4];
            float4 b0 = *(const float4*)&Bs[kk][tn * 8];
            float4 b1 = *(const float4*)&Bs[kk][tn * 8 + 4];
            unsigned long long bd[8];
            bd[0] = pack2(b0.x); bd[1] = pack2(b0.y); bd[2] = pack2(b0.z); bd[3] = pack2(b0.w);
            bd[4] = pack2(b1.x); bd[5] = pack2(b1.y); bd[6] = pack2(b1.z); bd[7] = pack2(b1.w);
            #pragma unroll
            for (int n = 0; n < 8; n++) {
                acc[0][n] = ffma2(aA.x, bd[n], acc[0][n]);
                acc[1][n] = ffma2(aA.y, bd[n], acc[1][n]);
                acc[2][n] = ffma2(aB.x, bd[n], acc[2][n]);
                acc[3][n] = ffma2(aB.y, bd[n], acc[3][n]);
            }
        }
        __syncthreads();
    }

    float4 bs0 = *(const float4*)&bias[n0 + tn * 8];
    float4 bs1 = *(const float4*)&bias[n0 + tn * 8 + 4];
    float bv[8] = {bs0.x, bs0.y, bs0.z, bs0.w, bs1.x, bs1.y, bs1.z, bs1.w};

    #pragma unroll
    for (int p = 0; p < 4; p++) {
        int r0 = m0 + tm * 8 + 2 * p;   // row pair (r0, r0+1)
        #pragma unroll
        for (int jj = 0; jj < 2; jj++) {
            float2 u0 = unpack2(acc[p][jj * 4 + 0]);
            float2 u1 = unpack2(acc[p][jj * 4 + 1]);
            float2 u2 = unpack2(acc[p][jj * 4 + 2]);
            float2 u3 = unpack2(acc[p][jj * 4 + 3]);
            float4 lo4, hi4;
            lo4.x = u0.x + bv[jj * 4 + 0]; hi4.x = u0.y + bv[jj * 4 + 0];
            lo4.y = u1.x + bv[jj * 4 + 1]; hi4.y = u1.y + bv[jj * 4 + 1];
            lo4.z = u2.x + bv[jj * 4 + 2]; hi4.z = u2.y + bv[jj * 4 + 2];
            lo4.w = u3.x + bv[jj * 4 + 3]; hi4.w = u3.y + bv[jj * 4 + 3];
            if (stage == 0) {
                lo4.x = tanh_(lo4.x); lo4.y = tanh_(lo4.y);
                lo4.z = tanh_(lo4.z); lo4.w = tanh_(lo4.w);
                hi4.x = tanh_(hi4.x); hi4.y = tanh_(hi4.y);
                hi4.z = tanh_(hi4.z); hi4.w = tanh_(hi4.w);
                int c0 = n0 + tn * 8 + jj * 4;
                *(float4*)(out + (size_t)r0 * 512 + c0)       = lo4;
                *(float4*)(out + (size_t)(r0 + 1) * 512 + c0) = hi4;
            } else {
                int b  = r0 >> 11;
                int t0 = r0 & 2047;
                int jglob = ((n0 + tn * 8) >> 2) + jj;
                *(float4*)(out + (((size_t)t0 * 512 + jglob) * 32 + b) * 4)       = lo4;
                *(float4*)(out + (((size_t)(t0 + 1) * 512 + jglob) * 32 + b) * 4) = hi4;
            }
        }
    }
}

// ---------------- persistent recurrent scan ----------------
// 128 CTAs x 256 threads; CTA owns 4 hidden cols j0..j0+3 (all 4 gates, all 32 b).
// SMEM: w_s [4j][512k] ulonglong2 gate-pairs (32768 B)
//       h_s per-warp [64k][36b] floats (73728 B)
//       part [8w][32b][4j] uint4 (16384 B) | c_s 128 floats (512 B) = 123392 B
#define H_S_OFF   32768
#define PART_OFF  106496
#define C_OFF     122880
#define SCAN_SMEM 123392

__global__ __launch_bounds__(256, 1) void lstm_scan_kernel(
    const float* __restrict__ Wf, const float* __restrict__ Wi,
    const float* __restrict__ Wc, const float* __restrict__ Wo,
    float* __restrict__ out) {
    extern __shared__ __align__(16) char smraw[];
    ulonglong2* w_s  = (ulonglong2*)smraw;                 // [j][k] gate-pairs
    float*      h_s  = (float*)(smraw + H_S_OFF);          // per warp [64][36]
    uint4*      part = (uint4*)(smraw + PART_OFF);         // [w][b][j]
    float*      c_s  = (float*)(smraw + C_OFF);            // [b*4+j]

    const int tid  = threadIdx.x;
    const int lane = tid & 31;
    const int wrp  = tid >> 5;
    const int j0   = blockIdx.x * 4;

    // cache recurrent weights (rows 512..1023), packed (f,i)(c,o) per (j,k)
    for (int idx = tid; idx < 4 * 512; idx += 256) {
        int j = idx >> 9, k = idx & 511;
        size_t off = (size_t)(512 + k) * HH + (j0 + j);
        uint4 w;
        w.x = __float_as_uint(Wf[off]); w.y = __float_as_uint(Wi[off]);
        w.z = __float_as_uint(Wc[off]); w.w = __float_as_uint(Wo[off]);
        ((uint4*)w_s)[j * 512 + k] = w;
    }
    if (tid < 128) c_s[tid] = 0.f;
    __syncthreads();

    float* my_h = h_s + wrp * (64 * 36);
    const ulonglong2* wp = w_s + wrp * 64;

    int cur = 0;
    for (int t = 0; t < TT; t++) {
        // prefetch this step's precomputed input-half pre-activations
        float4 pre4 = make_float4(0.f, 0.f, 0.f, 0.f);
        if (tid < 128) {
            int rj = tid & 3, rb = tid >> 2;
            pre4 = *(const float4*)(g_pre + (((size_t)t * 512 + j0 + rj) * 32 + rb) * 4);
        }

        // load this warp's h slice (k in [wrp*64, wrp*64+64), all 32 b) —
        // contiguous 8KB in [k][b] layout, coalesced, L1-bypassing (.cv)
        {
            const float* hg = g_hbuf[cur] + wrp * 2048;
            #pragma unroll
            for (int i = 0; i < 16; i++) {
                float4 v = ldcv4(hg + i * 128 + lane * 4);
                int k_local = i * 4 + (lane >> 3);
                int b4 = (lane & 7) * 4;
                *(float4*)(my_h + k_local * 36 + b4) = v;
            }
        }
        __syncwarp();

        // compute: lane = batch b, k slice of 64
        unsigned long long s00 = 0, s01 = 0, s10 = 0, s11 = 0;
        unsigned long long s20 = 0, s21 = 0, s30 = 0, s31 = 0;
        #pragma unroll 8
        for (int kk = 0; kk < 64; kk++) {
            unsigned long long hv = pack2(my_h[kk * 36 + lane]);
            ulonglong2 w0 = wp[kk];
            ulonglong2 w1 = wp[512 + kk];
            ulonglong2 w2 = wp[1024 + kk];
            ulonglong2 w3 = wp[1536 + kk];
            s00 = ffma2(hv, w0.x, s00); s01 = ffma2(hv, w0.y, s01);
            s10 = ffma2(hv, w1.x, s10); s11 = ffma2(hv, w1.y, s11);
            s20 = ffma2(hv, w2.x, s20); s21 = ffma2(hv, w2.y, s21);
            s30 = ffma2(hv, w3.x, s30); s31 = ffma2(hv, w3.y, s31);
        }
        {
            uint4* pp = part + (wrp * 32 + lane) * 4;
            float2 a, b2;
            a = unpack2(s00); b2 = unpack2(s01);
            pp[0] = make_uint4(__float_as_uint(a.x), __float_as_uint(a.y),
                               __float_as_uint(b2.x), __float_as_uint(b2.y));
            a = unpack2(s10); b2 = unpack2(s11);
            pp[1] = make_uint4(__float_as_uint(a.x), __float_as_uint(a.y),
                               __float_as_uint(b2.x), __float_as_uint(b2.y));
            a = unpack2(s20); b2 = unpack2(s21);
            pp[2] = make_uint4(__float_as_uint(a.x), __float_as_uint(a.y),
                               __float_as_uint(b2.x), __float_as_uint(b2.y));
            a = unpack2(s30); b2 = unpack2(s31);
            pp[3] = make_uint4(__float_as_uint(a.x), __float_as_uint(a.y),
                               __float_as_uint(b2.x), __float_as_uint(b2.y));
        }
        __syncthreads();

        int nxt = cur ^ 1;
        if (tid < 128) {
            int rj = tid & 3, rb = tid >> 2;
            float rf = 0.f, ri = 0.f, rc = 0.f, ro = 0.f;
            #pragma unroll
            for (int w = 0; w < 8; w++) {
                uint4 v = part[(w * 32 + rb) * 4 + rj];
                rf += __uint_as_float(v.x);
                ri += __uint_as_float(v.y);
                rc += __uint_as_float(v.z);
                ro += __uint_as_float(v.w);
            }
            float f  = sig_(pre4.x + rf);
            float ii = sig_(pre4.y + ri);
            float cg = tanh_(pre4.z + rc);
            float o  = sig_(pre4.w + ro);
            float cn = f * c_s[tid] + ii * cg;
            c_s[tid] = cn;
            float h = o * tanh_(cn);
            g_hbuf[nxt][(j0 + rj) * 32 + rb] = h;                 // [k][b] layout
            out[((size_t)rb * TT + t) * HH + j0 + rj] = h;
            __threadfence();   // release: drain h stores to L2 before the atomic
        }
        __syncthreads();

        // ---- proven atomic-counter grid barrier (as in passing R2) ----
        if (tid == 0) {
            atomicAdd(&g_bar, 1u);
            unsigned tgt = (unsigned)NCTA * (unsigned)(t + 1), v;
            do {
                asm volatile("ld.acquire.gpu.u32 %0, [%1];" : "=r"(v) : "l"(&g_bar) : "memory");
            } while (v < tgt);
        }
        __syncthreads();
        // no acquire-side __threadfence needed: h is re-read via ld.global.cv
        cur = nxt;
    }
}

extern "C" void kernel_launch(void* const* d_in, const int* in_sizes, int n_in,
                              void* d_out, int out_size) {
    const float* X   = (const float*)d_in[0];
    const float* W_p = (const float*)d_in[1];
    const float* b_p = (const float*)d_in[2];
    const float* W_f = (const float*)d_in[3];
    const float* b_f = (const float*)d_in[4];
    const float* W_i = (const float*)d_in[5];
    const float* b_i = (const float*)d_in[6];
    const float* W_c = (const float*)d_in[7];
    const float* b_c = (const float*)d_in[8];
    const float* W_o = (const float*)d_in[9];
    const float* b_o = (const float*)d_in[10];
    float* out = (float*)d_out;

    cudaFuncSetAttribute(lstm_scan_kernel,
                         cudaFuncAttributeMaxDynamicSharedMemorySize, SCAN_SMEM);

    pack_kernel<<<4096, 256>>>(W_f, W_i, W_c, W_o, b_f, b_i, b_c, b_o);
    gemm_kernel<<<dim3(4, 512), 256>>>(0, X, W_p, b_p);
    gemm_kernel<<<dim3(16, 512), 256>>>(1, nullptr, nullptr, nullptr);
    lstm_scan_kernel<<<NCTA, 256, SCAN_SMEM>>>(W_f, W_i, W_c, W_o, out);
}

// round 8
// speedup vs baseline: 1.1597x; 1.0018x over previous
#include <cuda_runtime.h>
#include <cuda_bf16.h>

#define TT    2048
#define BB    32
#define DD    512
#define HH    512
#define BTR   (BB * TT)          // 65536
#define NCTA  128

// ---------------- device scratch ----------------
__device__ float g_proj[(size_t)BTR * DD];               // 128 MB
__device__ float g_pre[(size_t)TT * HH * BB * 4];        // 512 MB  [t][j][b][gate]
__device__ float g_wcat[DD * 4 * HH];                    // 4 MB    [k][c], c = j*4+g
__device__ float g_bcat[4 * HH];
__device__ __align__(16) float g_hbuf[2][HH * BB];       // [k][b] layout
__device__ unsigned int g_bar;

// ---------------- packed f32x2 helpers ----------------
__device__ __forceinline__ unsigned long long ffma2(unsigned long long a,
                                                    unsigned long long b,
                                                    unsigned long long c) {
    unsigned long long d;
    asm("fma.rn.f32x2 %0, %1, %2, %3;" : "=l"(d) : "l"(a), "l"(b), "l"(c));
    return d;
}
__device__ __forceinline__ unsigned long long pack2(float x) {
    unsigned long long d;
    asm("mov.b64 %0, {%1, %1};" : "=l"(d) : "f"(x));
    return d;
}
__device__ __forceinline__ float2 unpack2(unsigned long long v) {
    float2 r;
    asm("mov.b64 {%0, %1}, %2;" : "=f"(r.x), "=f"(r.y) : "l"(v));
    return r;
}
__device__ __forceinline__ float4 ldcv4(const float* p) {
    float4 v;
    asm volatile("ld.global.cv.v4.f32 {%0,%1,%2,%3}, [%4];"
                 : "=f"(v.x), "=f"(v.y), "=f"(v.z), "=f"(v.w) : "l"(p));
    return v;
}

__device__ __forceinline__ float sig_(float x) {
    return __fdividef(1.f, 1.f + __expf(-x));
}
__device__ __forceinline__ float tanh_(float x) {
    return 1.f - __fdividef(2.f, __expf(2.f * x) + 1.f);
}

// ---------------- pack weights + init state ----------------
__global__ void pack_kernel(const float* __restrict__ Wf, const float* __restrict__ Wi,
                            const float* __restrict__ Wc, const float* __restrict__ Wo,
                            const float* __restrict__ bf, const float* __restrict__ bi,
                            const float* __restrict__ bc, const float* __restrict__ bo) {
    int idx = blockIdx.x * 256 + threadIdx.x;
    if (idx < DD * 4 * HH) {
        int k = idx >> 11;         // input-half row of W_*
        int c = idx & 2047;        // c = j*4+g
        int j = c >> 2, g = c & 3;
        const float* W = (g == 0) ? Wf : (g == 1) ? Wi : (g == 2) ? Wc : Wo;
        g_wcat[idx] = W[(size_t)k * HH + j];
    }
    if (idx < 4 * HH) {
        int j = idx >> 2, g = idx & 3;
        const float* bv = (g == 0) ? bf : (g == 1) ? bi : (g == 2) ? bc : bo;
        g_bcat[idx] = bv[j];
    }
    if (idx < HH * BB) g_hbuf[0][idx] = 0.f;
    if (idx == 0) g_bar = 0u;
}

// ---------------- fp32 SIMT GEMM, f32x2 accumulation ----------------
// C[M x N] = A[M x 512] * B[512 x N] (+bias). BM=BN=128, BK=16, 256 thr, 8x8 tiles.
// stage 0: A=X, B=W_p, ldb=512, out = g_proj[r*512+c] = tanh(.)
// stage 1: A=g_proj, B=g_wcat, ldb=2048, out = g_pre [t][j][b][g]
__global__ __launch_bounds__(256, 2) void gemm_kernel(
    int stage, const float* __restrict__ Aext, const float* __restrict__ Bext,
    const float* __restrict__ biasext) {
    __shared__ __align__(16) float As[16][132];
    __shared__ __align__(16) float Bs[16][128];

    const float* A    = (stage == 0) ? Aext    : g_proj;
    const float* B    = (stage == 0) ? Bext    : g_wcat;
    const float* bias = (stage == 0) ? biasext : g_bcat;
    float* out = (stage == 0) ? g_proj : g_pre;
    const int ldb = (stage == 0) ? 512 : 2048;

    const int tid = threadIdx.x;
    const int m0 = blockIdx.y * 128;
    const int n0 = blockIdx.x * 128;
    const int tm = tid >> 4, tn = tid & 15;

    unsigned long long acc[4][8];
    #pragma unroll
    for (int p = 0; p < 4; p++)
        #pragma unroll
        for (int n = 0; n < 8; n++) acc[p][n] = 0ull;

    for (int k0 = 0; k0 < 512; k0 += 16) {
        #pragma unroll
        for (int i = 0; i < 2; i++) {
            int idx = tid + i * 256;
            int row = idx >> 2, c4 = idx & 3;
            float4 v = *(const float4*)(A + (size_t)(m0 + row) * 512 + k0 + c4 * 4);
            As[c4 * 4 + 0][row] = v.x;
            As[c4 * 4 + 1][row] = v.y;
            As[c4 * 4 + 2][row] = v.z;
            As[c4 * 4 + 3][row] = v.w;
        }
        #pragma unroll
        for (int i = 0; i < 2; i++) {
            int idx = tid + i * 256;
            int row = idx >> 5, c4 = idx & 31;
            *(float4*)&Bs[row][c4 * 4] =
                *(const float4*)(B + (size_t)(k0 + row) * ldb + n0 + c4 * 4);
        }
        __syncthreads();
        #pragma unroll
        for (int kk = 0; kk < 16; kk++) {
            ulonglong2 aA = *(const ulonglong2*)&As[kk][tm * 8];
            ulonglong2 aB = *(const ulonglong2*)&As[kk][tm * 8 + 4];
            float4 b0 = *(const float4*)&Bs[kk][tn * 8];
            float4 b1 = *(const float4*)&Bs[kk][tn * 8 + 4];
            unsigned long long bd[8];
            bd[0] = pack2(b0.x); bd[1] = pack2(b0.y); bd[2] = pack2(b0.z); bd[3] = pack2(b0.w);
            bd[4] = pack2(b1.x); bd[5] = pack2(b1.y); bd[6] = pack2(b1.z); bd[7] = pack2(b1.w);
            #pragma unroll
            for (int n = 0; n < 8; n++) {
                acc[0][n] = ffma2(aA.x, bd[n], acc[0][n]);
                acc[1][n] = ffma2(aA.y, bd[n], acc[1][n]);
                acc[2][n] = ffma2(aB.x, bd[n], acc[2][n]);
                acc[3][n] = ffma2(aB.y, bd[n], acc[3][n]);
            }
        }
        __syncthreads();
    }

    float4 bs0 = *(const float4*)&bias[n0 + tn * 8];
    float4 bs1 = *(const float4*)&bias[n0 + tn * 8 + 4];
    float bv[8] = {bs0.x, bs0.y, bs0.z, bs0.w, bs1.x, bs1.y, bs1.z, bs1.w};

    #pragma unroll
    for (int p = 0; p < 4; p++) {
        int r0 = m0 + tm * 8 + 2 * p;   // row pair (r0, r0+1)
        #pragma unroll
        for (int jj = 0; jj < 2; jj++) {
            float2 u0 = unpack2(acc[p][jj * 4 + 0]);
            float2 u1 = unpack2(acc[p][jj * 4 + 1]);
            float2 u2 = unpack2(acc[p][jj * 4 + 2]);
            float2 u3 = unpack2(acc[p][jj * 4 + 3]);
            float4 lo4, hi4;
            lo4.x = u0.x + bv[jj * 4 + 0]; hi4.x = u0.y + bv[jj * 4 + 0];
            lo4.y = u1.x + bv[jj * 4 + 1]; hi4.y = u1.y + bv[jj * 4 + 1];
            lo4.z = u2.x + bv[jj * 4 + 2]; hi4.z = u2.y + bv[jj * 4 + 2];
            lo4.w = u3.x + bv[jj * 4 + 3]; hi4.w = u3.y + bv[jj * 4 + 3];
            if (stage == 0) {
                lo4.x = tanh_(lo4.x); lo4.y = tanh_(lo4.y);
                lo4.z = tanh_(lo4.z); lo4.w = tanh_(lo4.w);
                hi4.x = tanh_(hi4.x); hi4.y = tanh_(hi4.y);
                hi4.z = tanh_(hi4.z); hi4.w = tanh_(hi4.w);
                int c0 = n0 + tn * 8 + jj * 4;
                *(float4*)(out + (size_t)r0 * 512 + c0)       = lo4;
                *(float4*)(out + (size_t)(r0 + 1) * 512 + c0) = hi4;
            } else {
                int b  = r0 >> 11;
                int t0 = r0 & 2047;
                int jglob = ((n0 + tn * 8) >> 2) + jj;
                *(float4*)(out + (((size_t)t0 * 512 + jglob) * 32 + b) * 4)       = lo4;
                *(float4*)(out + (((size_t)(t0 + 1) * 512 + jglob) * 32 + b) * 4) = hi4;
            }
        }
    }
}

// ---------------- persistent recurrent scan ----------------
// 128 CTAs x 256 threads; CTA owns 4 hidden cols j0..j0+3 (all 4 gates, all 32 b).
// SMEM: w_s [4j][512k] ulonglong2 gate-pairs (32768 B)
//       h_s per-warp [64k][36b] floats (73728 B)
//       part [8w][32b][4j] uint4 (16384 B) | c_s 128 floats (512 B) = 123392 B
#define H_S_OFF   32768
#define PART_OFF  106496
#define C_OFF     122880
#define SCAN_SMEM 123392

__global__ __launch_bounds__(256, 1) void lstm_scan_kernel(
    const float* __restrict__ Wf, const float* __restrict__ Wi,
    const float* __restrict__ Wc, const float* __restrict__ Wo,
    float* __restrict__ out) {
    extern __shared__ __align__(16) char smraw[];
    ulonglong2* w_s  = (ulonglong2*)smraw;                 // [j][k] gate-pairs
    float*      h_s  = (float*)(smraw + H_S_OFF);          // per warp [64][36]
    uint4*      part = (uint4*)(smraw + PART_OFF);         // [w][b][j]
    float*      c_s  = (float*)(smraw + C_OFF);            // [b*4+j]

    const int tid  = threadIdx.x;
    const int lane = tid & 31;
    const int wrp  = tid >> 5;
    const int j0   = blockIdx.x * 4;

    // cache recurrent weights (rows 512..1023), packed (f,i)(c,o) per (j,k)
    for (int idx = tid; idx < 4 * 512; idx += 256) {
        int j = idx >> 9, k = idx & 511;
        size_t off = (size_t)(512 + k) * HH + (j0 + j);
        uint4 w;
        w.x = __float_as_uint(Wf[off]); w.y = __float_as_uint(Wi[off]);
        w.z = __float_as_uint(Wc[off]); w.w = __float_as_uint(Wo[off]);
        ((uint4*)w_s)[j * 512 + k] = w;
    }
    if (tid < 128) c_s[tid] = 0.f;
    __syncthreads();

    float* my_h = h_s + wrp * (64 * 36);
    const ulonglong2* wp = w_s + wrp * 64;

    int cur = 0;
    for (int t = 0; t < TT; t++) {
        // prefetch this step's precomputed input-half pre-activations
        float4 pre4 = make_float4(0.f, 0.f, 0.f, 0.f);
        if (tid < 128) {
            int rj = tid & 3, rb = tid >> 2;
            pre4 = *(const float4*)(g_pre + (((size_t)t * 512 + j0 + rj) * 32 + rb) * 4);
        }

        // load this warp's h slice (k in [wrp*64, wrp*64+64), all 32 b) —
        // contiguous 8KB in [k][b] layout, coalesced, L1-bypassing (.cv)
        {
            const float* hg = g_hbuf[cur] + wrp * 2048;
            #pragma unroll
            for (int i = 0; i < 16; i++) {
                float4 v = ldcv4(hg + i * 128 + lane * 4);
                int k_local = i * 4 + (lane >> 3);
                int b4 = (lane & 7) * 4;
                *(float4*)(my_h + k_local * 36 + b4) = v;
            }
        }
        __syncwarp();

        // compute: lane = batch b, k slice of 64
        unsigned long long s00 = 0, s01 = 0, s10 = 0, s11 = 0;
        unsigned long long s20 = 0, s21 = 0, s30 = 0, s31 = 0;
        #pragma unroll 8
        for (int kk = 0; kk < 64; kk++) {
            unsigned long long hv = pack2(my_h[kk * 36 + lane]);
            ulonglong2 w0 = wp[kk];
            ulonglong2 w1 = wp[512 + kk];
            ulonglong2 w2 = wp[1024 + kk];
            ulonglong2 w3 = wp[1536 + kk];
            s00 = ffma2(hv, w0.x, s00); s01 = ffma2(hv, w0.y, s01);
            s10 = ffma2(hv, w1.x, s10); s11 = ffma2(hv, w1.y, s11);
            s20 = ffma2(hv, w2.x, s20); s21 = ffma2(hv, w2.y, s21);
            s30 = ffma2(hv, w3.x, s30); s31 = ffma2(hv, w3.y, s31);
        }
        {
            uint4* pp = part + (wrp * 32 + lane) * 4;
            float2 a, b2;
            a = unpack2(s00); b2 = unpack2(s01);
            pp[0] = make_uint4(__float_as_uint(a.x), __float_as_uint(a.y),
                               __float_as_uint(b2.x), __float_as_uint(b2.y));
            a = unpack2(s10); b2 = unpack2(s11);
            pp[1] = make_uint4(__float_as_uint(a.x), __float_as_uint(a.y),
                               __float_as_uint(b2.x), __float_as_uint(b2.y));
            a = unpack2(s20); b2 = unpack2(s21);
            pp[2] = make_uint4(__float_as_uint(a.x), __float_as_uint(a.y),
                               __float_as_uint(b2.x), __float_as_uint(b2.y));
            a = unpack2(s30); b2 = unpack2(s31);
            pp[3] = make_uint4(__float_as_uint(a.x), __float_as_uint(a.y),
                               __float_as_uint(b2.x), __float_as_uint(b2.y));
        }
        __syncthreads();

        int nxt = cur ^ 1;
        if (tid < 128) {
            int rj = tid & 3, rb = tid >> 2;
            float rf = 0.f, ri = 0.f, rc = 0.f, ro = 0.f;
            #pragma unroll
            for (int w = 0; w < 8; w++) {
                uint4 v = part[(w * 32 + rb) * 4 + rj];
                rf += __uint_as_float(v.x);
                ri += __uint_as_float(v.y);
                rc += __uint_as_float(v.z);
                ro += __uint_as_float(v.w);
            }
            float f  = sig_(pre4.x + rf);
            float ii = sig_(pre4.y + ri);
            float cg = tanh_(pre4.z + rc);
            float o  = sig_(pre4.w + ro);
            float cn = f * c_s[tid] + ii * cg;
            c_s[tid] = cn;
            float h = o * tanh_(cn);
            g_hbuf[nxt][(j0 + rj) * 32 + rb] = h;                 // [k][b] layout
            out[((size_t)rb * TT + t) * HH + j0 + rj] = h;
            __threadfence();   // release: drain h stores to L2 before the atomic
        }
        __syncthreads();

        // ---- proven atomic-counter grid barrier (as in passing R2) ----
        if (tid == 0) {
            atomicAdd(&g_bar, 1u);
            unsigned tgt = (unsigned)NCTA * (unsigned)(t + 1), v;
            do {
                asm volatile("ld.acquire.gpu.u32 %0, [%1];" : "=r"(v) : "l"(&g_bar) : "memory");
            } while (v < tgt);
        }
        __syncthreads();
        // no acquire-side __threadfence needed: h is re-read via ld.global.cv
        cur = nxt;
    }
}

extern "C" void kernel_launch(void* const* d_in, const int* in_sizes, int n_in,
                              void* d_out, int out_size) {
    const float* X   = (const float*)d_in[0];
    const float* W_p = (const float*)d_in[1];
    const float* b_p = (const float*)d_in[2];
    const float* W_f = (const float*)d_in[3];
    const float* b_f = (const float*)d_in[4];
    const float* W_i = (const float*)d_in[5];
    const float* b_i = (const float*)d_in[6];
    const float* W_c = (const float*)d_in[7];
    const float* b_c = (const float*)d_in[8];
    const float* W_o = (const float*)d_in[9];
    const float* b_o = (const float*)d_in[10];
    float* out = (float*)d_out;

    cudaFuncSetAttribute(lstm_scan_kernel,
                         cudaFuncAttributeMaxDynamicSharedMemorySize, SCAN_SMEM);

    pack_kernel<<<4096, 256>>>(W_f, W_i, W_c, W_o, b_f, b_i, b_c, b_o);
    gemm_kernel<<<dim3(4, 512), 256>>>(0, X, W_p, b_p);
    gemm_kernel<<<dim3(16, 512), 256>>>(1, nullptr, nullptr, nullptr);
    lstm_scan_kernel<<<NCTA, 256, SCAN_SMEM>>>(W_f, W_i, W_c, W_o, out);
}